// round 10
// baseline (speedup 1.0000x reference)
#include <cuda_runtime.h>
#include <cuda_bf16.h>
#include <cstdint>

// AxonalConnections: out[b,t] = sum_s adj[t,s] * (1.5*E[s]-0.5) * spikes[b,s]
// adj is conv-pattern sparse (9 taps per target, boundary-clipped).
//
// R9 (re-bench; prior two rounds hit GPU-acquisition timeouts, kernel never ran)
//   = R3 (best measured: 256 CTAs x 512 thr, TPC=64, gather-once -> smem)
//   + stencil-shuffle phase 2: only the CENTER spike of each 3-tap row is
//     loaded (12 coalesced LDG/thread instead of 36); left/right neighbors
//     come from __shfl_up/down, with predicated single-lane halo loads at
//     warp edges. Grid-edge columns are covered by exactly-zero weights.

#define HW 128
#define S_TOT (HW * HW)      // 16384
#define B_TOT 32
#define TPC 64               // targets per CTA (one half-row; ti constant)
#define THREADS 512
#define BPT 4                // batches per thread (8 batch groups)
#define FULLMASK 0xffffffffu

__global__ __launch_bounds__(THREADS)
void axonal_r9_kernel(const float* __restrict__ spikes,   // [B, 16384]
                      const float* __restrict__ E,        // [16384]
                      const float* __restrict__ adj,      // [16384, 16384]
                      float* __restrict__ out)            // [B, 16384]
{
    __shared__ float wsm[9 * TPC];       // [k][tloc] folded weights

    const int tid = threadIdx.x;
    const int t0  = blockIdx.x * TPC;    // 64 | t0, so ti is constant per CTA
    const int ti  = t0 >> 7;

    // ---- Phase 1: gather 3 adjacent adj taps + E per thread, fold ----
    if (tid < 3 * TPC) {
        const int tloc = tid & (TPC - 1);
        const int ki   = tid / TPC;              // 0..2
        const int t    = t0 + tloc;
        const int tj   = t & (HW - 1);
        const int si   = ti - 1 + ki;
        const bool rowok = (si >= 0) & (si < HW);
        const size_t rowbase = (size_t)t * S_TOT + (size_t)(si * HW);
#pragma unroll
        for (int kj = 0; kj < 3; ++kj) {
            const int sj = tj - 1 + kj;
            const bool ok = rowok & (sj >= 0) & (sj < HW);
            float w = 0.0f;
            if (ok) {
                const int s = si * HW + sj;
                w = __ldg(&adj[rowbase + (size_t)sj]) *
                    (1.5f * __ldg(&E[s]) - 0.5f);
            }
            wsm[(ki * 3 + kj) * TPC + tloc] = w;
        }
    }
    __syncthreads();

    // ---- Phase 2: center-load + shuffle stencil ----
    const int tloc = tid & (TPC - 1);    // warp spans 32 consecutive columns
    const int bg   = tid / TPC;          // 0..7
    const int lane = tid & 31;
    const int t    = t0 + tloc;
    const int tj   = t & (HW - 1);

    float w[9];
#pragma unroll
    for (int k = 0; k < 9; ++k)
        w[k] = wsm[k * TPC + tloc];      // conflict-free broadcast

    // Center / halo indices per ki (clamped in-bounds; clipped taps have w=0).
    int sc[3], sleft[3], sright[3];
#pragma unroll
    for (int ki = 0; ki < 3; ++ki) {
        const int si = ti - 1 + ki;
        const bool rowok = (si >= 0) & (si < HW);
        const int base = rowok ? si * HW : 0;    // safe row
        sc[ki]     = base + tj;
        sleft[ki]  = base + (tj > 0 ? tj - 1 : 0);        // lane 0 halo
        sright[ki] = base + (tj < HW - 1 ? tj + 1 : tj);  // lane 31 halo
    }

    // Issue all 12 center loads up front (independent, coalesced).
    float v[BPT][3];
#pragma unroll
    for (int bb = 0; bb < BPT; ++bb) {
        const float* __restrict__ sp = spikes + (size_t)(bg * BPT + bb) * S_TOT;
#pragma unroll
        for (int ki = 0; ki < 3; ++ki)
            v[bb][ki] = __ldg(&sp[sc[ki]]);
    }

#pragma unroll
    for (int bb = 0; bb < BPT; ++bb) {
        const int b = bg * BPT + bb;
        const float* __restrict__ sp = spikes + (size_t)b * S_TOT;
        float a0 = 0.f, a1 = 0.f, a2 = 0.f;
#pragma unroll
        for (int ki = 0; ki < 3; ++ki) {
            const float vc = v[bb][ki];
            float vl = __shfl_up_sync(FULLMASK, vc, 1);
            float vr = __shfl_down_sync(FULLMASK, vc, 1);
            if (lane == 0)  vl = __ldg(&sp[sleft[ki]]);   // warp-edge halo
            if (lane == 31) vr = __ldg(&sp[sright[ki]]);
            a0 = fmaf(w[ki * 3 + 0], vl, a0);
            a1 = fmaf(w[ki * 3 + 1], vc, a1);
            a2 = fmaf(w[ki * 3 + 2], vr, a2);
        }
        out[(size_t)b * S_TOT + t] = a0 + a1 + a2;
    }
}

extern "C" void kernel_launch(void* const* d_in, const int* in_sizes, int n_in,
                              void* d_out, int out_size)
{
    // Identify inputs by element count:
    //   spikes: 524288, E: 16384, adjacency: 268435456
    const float* spikes = nullptr;
    const float* E      = nullptr;
    const float* adj    = nullptr;
    for (int i = 0; i < n_in; ++i) {
        if (in_sizes[i] == B_TOT * S_TOT)  spikes = (const float*)d_in[i];
        else if (in_sizes[i] == S_TOT)     E      = (const float*)d_in[i];
        else                               adj    = (const float*)d_in[i];
    }
    float* out = (float*)d_out;

    axonal_r9_kernel<<<S_TOT / TPC, THREADS>>>(spikes, E, adj, out);  // 256 CTAs
}